// round 7
// baseline (speedup 1.0000x reference)
#include <cuda_runtime.h>

// ---------------------------------------------------------------------------
// SpatioTemporalGNNLayer: out = relu(conv3x3(x,Ww)+Wb + conv3x3(agg,Bw)+Bb)
// agg[dst] = mean over incoming edges of x[src].
//
// CSR build, then one fused per-node kernel. Conv uses fma.rn.f32x2 with
// dual-alignment smem rows. 256 threads/CTA x 2 CTAs/SM (16 warps) for
// latency hiding; warp = 8 rows x 4 cos so every image load is a single
// conflict-free 128B wavefront. Weight taps packed contiguously per (ci,r,co).
// ---------------------------------------------------------------------------

#define NNODES 4096
#define NODE_ELEMS 4096          // 16*16*16
#define RS 36                    // row: [0,x0..x15,0,pad,pad | x0..x15] (144B)
#define CHS (18*RS)              // 18 rows (zero row above+below) = 648 floats
#define IMG_FLOATS (32*CHS)      // 20736 (x image 16ch + agg image 16ch)
#define WT_FLOAT2 3072           // 16ci*3r*16co*4(t0,t1,t2,pad) float2 = 24KB
#define NMASK (NNODES-1)

__device__ int g_deg[NNODES];
__device__ int g_cur[NNODES];
__device__ int g_off[NNODES + 1];
__device__ int g_srcs[16384 * 4];
__device__ int g_is64;

// ---------------------------------------------------------------------------
__global__ void prep_kernel(const int* __restrict__ ei32, int E) {
    int i = blockIdx.x * blockDim.x + threadIdx.x;
    if (i < NNODES) { g_deg[i] = 0; g_cur[i] = 0; }
    if (blockIdx.x == 0 && threadIdx.x < 32) {
        int n = (E < 32) ? E : 32;
        int odd = (threadIdx.x < n) ? ei32[2 * threadIdx.x + 1] : 0;
        unsigned nz = __ballot_sync(0xffffffffu, odd != 0);
        if (threadIdx.x == 0) g_is64 = (nz == 0);
    }
}

__device__ __forceinline__ int load_idx(const int* ei32, int pos) {
    return g_is64 ? (ei32[2 * pos] & NMASK) : (ei32[pos] & NMASK);
}

__global__ void count_kernel(const int* __restrict__ ei32, int E) {
    int e = blockIdx.x * blockDim.x + threadIdx.x;
    if (e < E) atomicAdd(&g_deg[load_idx(ei32, E + e)], 1);
}

__global__ void scanfill_kernel(const int* __restrict__ ei32, int E) {
    __shared__ int wsum[32];
    int t = threadIdx.x;
    int lane = t & 31, wid = t >> 5;
    int4 v = ((const int4*)g_deg)[t];
    int sum = v.x + v.y + v.z + v.w;
    int s = sum;
#pragma unroll
    for (int d = 1; d < 32; d <<= 1) {
        int n = __shfl_up_sync(0xffffffffu, s, d);
        if (lane >= d) s += n;
    }
    if (lane == 31) wsum[wid] = s;
    __syncthreads();
    if (wid == 0) {
        int ws = wsum[lane];
#pragma unroll
        for (int d = 1; d < 32; d <<= 1) {
            int n = __shfl_up_sync(0xffffffffu, ws, d);
            if (lane >= d) ws += n;
        }
        wsum[lane] = ws;
    }
    __syncthreads();
    int excl = ((wid > 0) ? wsum[wid - 1] : 0) + s - sum;
    g_off[4 * t + 0] = excl;
    g_off[4 * t + 1] = excl + v.x;
    g_off[4 * t + 2] = excl + v.x + v.y;
    g_off[4 * t + 3] = excl + v.x + v.y + v.z;
    if (t == 1023) g_off[NNODES] = wsum[31];
    __syncthreads();
    for (int e = t; e < E; e += 1024) {
        int sc = load_idx(ei32, e);
        int d  = load_idx(ei32, E + e);
        int pos = g_off[d] + atomicAdd(&g_cur[d], 1);
        g_srcs[pos] = sc;
    }
}

// ---------------------------------------------------------------------------
__device__ __forceinline__ float2 ffma2(float2 a, float2 b, float2 c) {
    float2 d;
    asm("{\n\t"
        ".reg .b64 ta, tb, tc;\n\t"
        "mov.b64 ta, {%2, %3};\n\t"
        "mov.b64 tb, {%4, %5};\n\t"
        "mov.b64 tc, {%6, %7};\n\t"
        "fma.rn.f32x2 tc, ta, tb, tc;\n\t"
        "mov.b64 {%0, %1}, tc;\n\t"
        "}"
        : "=f"(d.x), "=f"(d.y)
        : "f"(a.x), "f"(a.y), "f"(b.x), "f"(b.y), "f"(c.x), "f"(c.y));
    return d;
}

// One conv over a 16-channel image: this thread's 1 output channel x 16 px
// (8 pixel pairs) of one output row.
// Row layout (36 floats): [0, x0..x15, 0, pad, pad, x0..x15]
//   P[k] = {x_{2k-1}, x_{2k}} at words 2k (taps -1/+1), k=0..8
//   S[k] = {x_{2k},  x_{2k+1}} at words 20+2k (tap 0),  k=0..7
// Weight pairs wt[((ci*3+r)*16 + co)*4 + t] = (w,w), t=0..2 (+pad).
__device__ __forceinline__ void conv_phase(const float* __restrict__ img,
                                           const float2* __restrict__ wt,
                                           int row, int co, float2 acc[8]) {
#pragma unroll 1
    for (int ci = 0; ci < 16; ci++) {
        const float* ch = img + ci * CHS;
#pragma unroll
        for (int r = 0; r < 3; r++) {
            const float* rp = ch + (row + r) * RS;
            float4 p0 = *(const float4*)(rp);
            float4 p1 = *(const float4*)(rp + 4);
            float4 p2 = *(const float4*)(rp + 8);
            float4 p3 = *(const float4*)(rp + 12);
            float2 p4 = *(const float2*)(rp + 16);
            float4 s0 = *(const float4*)(rp + 20);
            float4 s1 = *(const float4*)(rp + 24);
            float4 s2 = *(const float4*)(rp + 28);
            float4 s3 = *(const float4*)(rp + 32);
            float2 P[9] = { make_float2(p0.x, p0.y), make_float2(p0.z, p0.w),
                            make_float2(p1.x, p1.y), make_float2(p1.z, p1.w),
                            make_float2(p2.x, p2.y), make_float2(p2.z, p2.w),
                            make_float2(p3.x, p3.y), make_float2(p3.z, p3.w),
                            p4 };
            float2 S[8] = { make_float2(s0.x, s0.y), make_float2(s0.z, s0.w),
                            make_float2(s1.x, s1.y), make_float2(s1.z, s1.w),
                            make_float2(s2.x, s2.y), make_float2(s2.z, s2.w),
                            make_float2(s3.x, s3.y), make_float2(s3.z, s3.w) };
            const float2* wr = wt + ((ci * 3 + r) * 16 + co) * 4;
            float4 w01 = *(const float4*)wr;     // taps 0,1 duplicated
            float2 w2v = *(const float2*)(wr + 2);
            float2 w0 = make_float2(w01.x, w01.y);
            float2 w1 = make_float2(w01.z, w01.w);
#pragma unroll
            for (int j = 0; j < 8; j++) {
                acc[j] = ffma2(w0, P[j],     acc[j]);
                acc[j] = ffma2(w1, S[j],     acc[j]);
                acc[j] = ffma2(w2v, P[j + 1], acc[j]);
            }
        }
    }
}

__global__ __launch_bounds__(256, 2) void gnn_main_kernel(
    const float* __restrict__ x,
    const float* __restrict__ Ww, const float* __restrict__ Wbias,
    const float* __restrict__ Bw, const float* __restrict__ Bbias,
    float* __restrict__ out) {
    extern __shared__ float sm[];
    float*  sImg = sm;                          // 20736 floats
    float2* sWt  = (float2*)(sm + IMG_FLOATS);  // 3072 float2 (one conv)

    int tid  = threadIdx.x;
    int node = blockIdx.x;

    // zero image buffers (pads stay 0)
    float4* z4 = (float4*)sImg;
    for (int i = tid; i < IMG_FLOATS / 4; i += 256)
        z4[i] = make_float4(0.f, 0.f, 0.f, 0.f);
    // stage phase-A (Ww) taps: wt[((ci*3+r)*16+co)*4+t] = (w,w)
    for (int i = tid; i < WT_FLOAT2; i += 256) {
        int t  = i & 3;
        int co = (i >> 2) & 15;
        int q3 = i >> 6;                 // ci*3 + r
        float v = (t < 3) ? Ww[co * 144 + q3 * 3 + t] : 0.f;
        sWt[i] = make_float2(v, v);
    }

    // gather-mean over incoming edges: 4 float4 per thread (regs)
    const float4* xp = (const float4*)(x + (size_t)node * NODE_ELEMS);
    float4 a[4];
#pragma unroll
    for (int k = 0; k < 4; k++) a[k] = make_float4(0.f, 0.f, 0.f, 0.f);
    int beg = g_off[node], end = g_off[node + 1];
    for (int e = beg; e < end; e++) {
        int sc = g_srcs[e] & NMASK;
        const float4* sp = (const float4*)(x + (size_t)sc * NODE_ELEMS);
#pragma unroll
        for (int k = 0; k < 4; k++) {
            float4 v = __ldg(&sp[tid + 256 * k]);
            a[k].x += v.x; a[k].y += v.y; a[k].z += v.z; a[k].w += v.w;
        }
    }
    float inv = 1.0f / (float)max(end - beg, 1);

    __syncthreads();   // zeros + Ww taps in place

    // scatter x + agg into dual-alignment rows
#pragma unroll
    for (int k = 0; k < 4; k++) {
        int i4  = tid + 256 * k;
        int ci  = i4 >> 6;
        int rem = i4 & 63;
        int y   = rem >> 2;
        int m   = (rem & 3) * 4;
        float* bx = sImg + ci * CHS + (y + 1) * RS;
        float* ba = sImg + (16 + ci) * CHS + (y + 1) * RS;
        float4 xv = xp[i4];
        bx[1 + m] = xv.x; bx[2 + m] = xv.y; bx[3 + m] = xv.z; bx[4 + m] = xv.w;
        *(float4*)(bx + 20 + m) = xv;
        float4 av = make_float4(a[k].x * inv, a[k].y * inv, a[k].z * inv, a[k].w * inv);
        ba[1 + m] = av.x; ba[2 + m] = av.y; ba[3 + m] = av.z; ba[4 + m] = av.w;
        *(float4*)(ba + 20 + m) = av;
    }
    __syncthreads();

    // thread map: warp = 8 rows x 4 cos -> image loads 1 wavefront each
    int lane = tid & 31;
    int w    = tid >> 5;
    int row  = (lane & 7) | ((w & 1) << 3);
    int co   = ((lane >> 3) & 3) | ((w >> 1) << 2);

    float2 acc[8];
    float bz = __ldg(&Wbias[co]) + __ldg(&Bbias[co]);
#pragma unroll
    for (int j = 0; j < 8; j++) acc[j] = make_float2(bz, bz);

    // phase A: conv(x, Ww)
    conv_phase(sImg, sWt, row, co, acc);

    __syncthreads();   // done reading Ww taps
    for (int i = tid; i < WT_FLOAT2; i += 256) {
        int t  = i & 3;
        int c2 = (i >> 2) & 15;
        int q3 = i >> 6;
        float v = (t < 3) ? Bw[c2 * 144 + q3 * 3 + t] : 0.f;
        sWt[i] = make_float2(v, v);
    }
    __syncthreads();

    // phase B: conv(agg, Bw)
    conv_phase(sImg + 16 * CHS, sWt, row, co, acc);

    // relu + store: 16 px of one co
    float* o = out + (size_t)node * NODE_ELEMS + co * 256 + row * 16;
#pragma unroll
    for (int q = 0; q < 4; q++) {
        ((float4*)o)[q] = make_float4(
            fmaxf(acc[2 * q].x, 0.f), fmaxf(acc[2 * q].y, 0.f),
            fmaxf(acc[2 * q + 1].x, 0.f), fmaxf(acc[2 * q + 1].y, 0.f));
    }
}

// ---------------------------------------------------------------------------
extern "C" void kernel_launch(void* const* d_in, const int* in_sizes, int n_in,
                              void* d_out, int out_size) {
    const float* x   = (const float*)d_in[0];
    const int*   ei  = (const int*)d_in[1];   // int32 view; prep detects dtype
    const float* Ww  = (const float*)d_in[2];
    const float* Wb  = (const float*)d_in[3];
    const float* Bw  = (const float*)d_in[4];
    const float* Bb  = (const float*)d_in[5];
    float*       out = (float*)d_out;

    int E = in_sizes[1] / 2;
    int N = in_sizes[0] / NODE_ELEMS;

    prep_kernel<<<(NNODES + 255) / 256, 256>>>(ei, E);
    count_kernel<<<(E + 255) / 256, 256>>>(ei, E);
    scanfill_kernel<<<1, 1024>>>(ei, E);

    int smem_bytes = (IMG_FLOATS + 2 * WT_FLOAT2) * (int)sizeof(float);  // 107520
    cudaFuncSetAttribute(gnn_main_kernel,
                         cudaFuncAttributeMaxDynamicSharedMemorySize, smem_bytes);
    gnn_main_kernel<<<N, 256, smem_bytes>>>(x, Ww, Wb, Bw, Bb, out);
}

// round 8
// speedup vs baseline: 1.5952x; 1.5952x over previous
#include <cuda_runtime.h>

// ---------------------------------------------------------------------------
// SpatioTemporalGNNLayer: out = relu(conv3x3(x,Ww)+Wb + conv3x3(agg,Bw)+Bb)
// agg[dst] = mean over incoming edges of x[src].
//
// Fused per-node kernel. fma.rn.f32x2 conv with dual-alignment smem rows.
// Crossbar-byte-aware decomposition: thread = 4 cos x 8 px (image bytes /4),
// warp-uniform weights (broadcast LDS = 1 wavefront), warps split ci halves,
// cross-warp reduction in smem. 256 thr x 2 CTAs/SM.
// ---------------------------------------------------------------------------

#define NNODES 4096
#define NODE_ELEMS 4096          // 16*16*16
#define RS 36                    // row: [0,x0..x15,0,pad,pad | x0..x15] (144B)
#define CHS (18*RS)              // 18 rows = 648 floats
#define IMG_FLOATS (32*CHS)      // 20736 (x 16ch + agg 16ch)
#define WT_FLOAT2 2304           // 16ci*3r*4g*12 packed pairs (one conv)
#define NMASK (NNODES-1)

__device__ int g_deg[NNODES];
__device__ int g_cur[NNODES];
__device__ int g_off[NNODES + 1];
__device__ int g_srcs[16384 * 4];
__device__ int g_is64;

// ---------------------------------------------------------------------------
__global__ void prep_kernel(const int* __restrict__ ei32, int E) {
    int i = blockIdx.x * blockDim.x + threadIdx.x;
    if (i < NNODES) { g_deg[i] = 0; g_cur[i] = 0; }
    if (blockIdx.x == 0 && threadIdx.x < 32) {
        int n = (E < 32) ? E : 32;
        int odd = (threadIdx.x < n) ? ei32[2 * threadIdx.x + 1] : 0;
        unsigned nz = __ballot_sync(0xffffffffu, odd != 0);
        if (threadIdx.x == 0) g_is64 = (nz == 0);
    }
}

__device__ __forceinline__ int load_idx(const int* ei32, int pos) {
    return g_is64 ? (ei32[2 * pos] & NMASK) : (ei32[pos] & NMASK);
}

__global__ void count_kernel(const int* __restrict__ ei32, int E) {
    int e = blockIdx.x * blockDim.x + threadIdx.x;
    if (e < E) atomicAdd(&g_deg[load_idx(ei32, E + e)], 1);
}

__global__ void scanfill_kernel(const int* __restrict__ ei32, int E) {
    __shared__ int wsum[32];
    int t = threadIdx.x;
    int lane = t & 31, wid = t >> 5;
    int4 v = ((const int4*)g_deg)[t];
    int sum = v.x + v.y + v.z + v.w;
    int s = sum;
#pragma unroll
    for (int d = 1; d < 32; d <<= 1) {
        int n = __shfl_up_sync(0xffffffffu, s, d);
        if (lane >= d) s += n;
    }
    if (lane == 31) wsum[wid] = s;
    __syncthreads();
    if (wid == 0) {
        int ws = wsum[lane];
#pragma unroll
        for (int d = 1; d < 32; d <<= 1) {
            int n = __shfl_up_sync(0xffffffffu, ws, d);
            if (lane >= d) ws += n;
        }
        wsum[lane] = ws;
    }
    __syncthreads();
    int excl = ((wid > 0) ? wsum[wid - 1] : 0) + s - sum;
    g_off[4 * t + 0] = excl;
    g_off[4 * t + 1] = excl + v.x;
    g_off[4 * t + 2] = excl + v.x + v.y;
    g_off[4 * t + 3] = excl + v.x + v.y + v.z;
    if (t == 1023) g_off[NNODES] = wsum[31];
    __syncthreads();
    for (int e = t; e < E; e += 1024) {
        int sc = load_idx(ei32, e);
        int d  = load_idx(ei32, E + e);
        int pos = g_off[d] + atomicAdd(&g_cur[d], 1);
        g_srcs[pos] = sc;
    }
}

// ---------------------------------------------------------------------------
__device__ __forceinline__ float2 ffma2(float2 a, float2 b, float2 c) {
    float2 d;
    asm("{\n\t"
        ".reg .b64 ta, tb, tc;\n\t"
        "mov.b64 ta, {%2, %3};\n\t"
        "mov.b64 tb, {%4, %5};\n\t"
        "mov.b64 tc, {%6, %7};\n\t"
        "fma.rn.f32x2 tc, ta, tb, tc;\n\t"
        "mov.b64 {%0, %1}, tc;\n\t"
        "}"
        : "=f"(d.x), "=f"(d.y)
        : "f"(a.x), "f"(a.y), "f"(b.x), "f"(b.y), "f"(c.x), "f"(c.y));
    return d;
}

// 8-ci-slice conv: this thread's 4 output channels (co = 4g..4g+3) x 8 px
// (pixel pairs jj = 4*half + j) of one output row.
// Row layout (36 floats): [0, x0..x15, 0, pad, pad, x0..x15]
//   P[k] = {x_{2k-1}, x_{2k}} at words 2k;  S[k] = {x_{2k}, x_{2k+1}} at 20+2k.
// Weights wt[((ci*3+r)*4+g)*12 + t*4 + c] = (w,w), warp-uniform address.
__device__ __forceinline__ void conv_slice(const float* __restrict__ img,
                                           const float2* __restrict__ wt,
                                           int ci0, int row, int half, int g,
                                           float2 acc[4][4]) {
#pragma unroll 1
    for (int cl = 0; cl < 8; cl++) {
        int ci = ci0 + cl;
        const float* ch = img + ci * CHS;
#pragma unroll
        for (int r = 0; r < 3; r++) {
            const float* bp = ch + (row + r) * RS;
            // image: 5 loads, 72B per lane (all lanes distinct -> 18 wf/warp)
            float4 pa = *(const float4*)(bp + 8 * half);
            float4 pb = *(const float4*)(bp + 8 * half + 4);
            float2 pc = *(const float2*)(bp + 8 * half + 8);
            float4 sa = *(const float4*)(bp + 20 + 8 * half);
            float4 sb = *(const float4*)(bp + 24 + 8 * half);
            float2 P[5] = { make_float2(pa.x, pa.y), make_float2(pa.z, pa.w),
                            make_float2(pb.x, pb.y), make_float2(pb.z, pb.w),
                            pc };
            float2 S[4] = { make_float2(sa.x, sa.y), make_float2(sa.z, sa.w),
                            make_float2(sb.x, sb.y), make_float2(sb.z, sb.w) };
            // weights: warp-uniform broadcast loads (6 x LDS.128 = 6 wf)
            const float2* wr = wt + ((ci * 3 + r) * 4 + g) * 12;
#pragma unroll
            for (int t = 0; t < 3; t++) {
                float4 w01 = *(const float4*)(wr + t * 4);
                float4 w23 = *(const float4*)(wr + t * 4 + 2);
                float2 w[4] = { make_float2(w01.x, w01.y), make_float2(w01.z, w01.w),
                                make_float2(w23.x, w23.y), make_float2(w23.z, w23.w) };
#pragma unroll
                for (int c = 0; c < 4; c++) {
#pragma unroll
                    for (int j = 0; j < 4; j++) {
                        float2 op = (t == 0) ? P[j] : (t == 1) ? S[j] : P[j + 1];
                        acc[c][j] = ffma2(w[c], op, acc[c][j]);
                    }
                }
            }
        }
    }
}

__global__ __launch_bounds__(256, 2) void gnn_main_kernel(
    const float* __restrict__ x,
    const float* __restrict__ Ww, const float* __restrict__ Wbias,
    const float* __restrict__ Bw, const float* __restrict__ Bbias,
    float* __restrict__ out) {
    extern __shared__ float sm[];
    float*  sImg = sm;                          // 20736 floats
    float2* sWt  = (float2*)(sm + IMG_FLOATS);  // 2304 float2 (one conv)

    int tid  = threadIdx.x;
    int node = blockIdx.x;

    // zero image buffers (pads stay 0)
    float4* z4 = (float4*)sImg;
    for (int i = tid; i < IMG_FLOATS / 4; i += 256)
        z4[i] = make_float4(0.f, 0.f, 0.f, 0.f);
    // stage phase-A (Ww): wt[((ci*3+r)*4+g)*12 + t*4 + c] = (w,w)
    for (int i = tid; i < WT_FLOAT2; i += 256) {
        int p12 = i % 12, rest = i / 12;
        int t = p12 >> 2, c = p12 & 3;
        int gg = rest & 3, q = rest >> 2;          // q = ci*3 + r
        int ci = q / 3, r = q % 3;
        float v = Ww[(4 * gg + c) * 144 + ci * 9 + r * 3 + t];
        sWt[i] = make_float2(v, v);
    }

    // gather-mean over incoming edges: 4 float4 per thread (regs)
    const float4* xp = (const float4*)(x + (size_t)node * NODE_ELEMS);
    float4 a[4];
#pragma unroll
    for (int k = 0; k < 4; k++) a[k] = make_float4(0.f, 0.f, 0.f, 0.f);
    int beg = g_off[node], end = g_off[node + 1];
    for (int e = beg; e < end; e++) {
        int sc = g_srcs[e] & NMASK;
        const float4* sp = (const float4*)(x + (size_t)sc * NODE_ELEMS);
#pragma unroll
        for (int k = 0; k < 4; k++) {
            float4 v = __ldg(&sp[tid + 256 * k]);
            a[k].x += v.x; a[k].y += v.y; a[k].z += v.z; a[k].w += v.w;
        }
    }
    float inv = 1.0f / (float)max(end - beg, 1);

    __syncthreads();   // zeros + Ww staged

    // scatter x + agg into dual-alignment rows
#pragma unroll
    for (int k = 0; k < 4; k++) {
        int i4  = tid + 256 * k;
        int ci  = i4 >> 6;
        int rem = i4 & 63;
        int y   = rem >> 2;
        int m   = (rem & 3) * 4;
        float* bx = sImg + ci * CHS + (y + 1) * RS;
        float* ba = sImg + (16 + ci) * CHS + (y + 1) * RS;
        float4 xv = xp[i4];
        bx[1 + m] = xv.x; bx[2 + m] = xv.y; bx[3 + m] = xv.z; bx[4 + m] = xv.w;
        *(float4*)(bx + 20 + m) = xv;
        float4 av = make_float4(a[k].x * inv, a[k].y * inv, a[k].z * inv, a[k].w * inv);
        ba[1 + m] = av.x; ba[2 + m] = av.y; ba[3 + m] = av.z; ba[4 + m] = av.w;
        *(float4*)(ba + 20 + m) = av;
    }
    __syncthreads();

    // thread map: warp w -> co-group g = w&3, ci half ci0 = (w>>2)*8
    //             lane   -> row = lane&15, half = lane>>4
    int lane = tid & 31;
    int w    = tid >> 5;
    int row  = lane & 15;
    int half = lane >> 4;
    int g    = w & 3;
    int ci0  = (w >> 2) * 8;

    float2 acc[4][4];
#pragma unroll
    for (int c = 0; c < 4; c++)
#pragma unroll
        for (int j = 0; j < 4; j++) acc[c][j] = make_float2(0.f, 0.f);

    // phase A: conv(x, Ww) over this warp's ci slice
    conv_slice(sImg, sWt, ci0, row, half, g, acc);

    __syncthreads();   // done reading Ww
    for (int i = tid; i < WT_FLOAT2; i += 256) {
        int p12 = i % 12, rest = i / 12;
        int t = p12 >> 2, c = p12 & 3;
        int gg = rest & 3, q = rest >> 2;
        int ci = q / 3, r = q % 3;
        float v = Bw[(4 * gg + c) * 144 + ci * 9 + r * 3 + t];
        sWt[i] = make_float2(v, v);
    }
    __syncthreads();

    // phase B: conv(agg, Bw)
    conv_slice(sImg + 16 * CHS, sWt, ci0, row, half, g, acc);

    // cross-warp reduction: warps 4-7 dump partials into smem (SoA float4,
    // conflict-free), warps 0-3 add, then bias + relu + store.
    __syncthreads();   // image reads complete; safe to reuse sImg
    float4* red = (float4*)sImg;   // 128 slots x 8 float4
    if (w >= 4) {
        int slot = tid - 128;
#pragma unroll
        for (int c = 0; c < 4; c++) {
            red[(2 * c + 0) * 128 + slot] =
                make_float4(acc[c][0].x, acc[c][0].y, acc[c][1].x, acc[c][1].y);
            red[(2 * c + 1) * 128 + slot] =
                make_float4(acc[c][2].x, acc[c][2].y, acc[c][3].x, acc[c][3].y);
        }
    }
    __syncthreads();
    if (w < 4) {
        int slot = tid;
#pragma unroll
        for (int c = 0; c < 4; c++) {
            int co = 4 * g + c;
            float bz = __ldg(&Wbias[co]) + __ldg(&Bbias[co]);
            float4 r0 = red[(2 * c + 0) * 128 + slot];
            float4 r1 = red[(2 * c + 1) * 128 + slot];
            float* o = out + (size_t)node * NODE_ELEMS + co * 256
                       + row * 16 + 8 * half;
            ((float4*)o)[0] = make_float4(
                fmaxf(acc[c][0].x + r0.x + bz, 0.f),
                fmaxf(acc[c][0].y + r0.y + bz, 0.f),
                fmaxf(acc[c][1].x + r0.z + bz, 0.f),
                fmaxf(acc[c][1].y + r0.w + bz, 0.f));
            ((float4*)o)[1] = make_float4(
                fmaxf(acc[c][2].x + r1.x + bz, 0.f),
                fmaxf(acc[c][2].y + r1.y + bz, 0.f),
                fmaxf(acc[c][3].x + r1.z + bz, 0.f),
                fmaxf(acc[c][3].y + r1.w + bz, 0.f));
        }
    }
}

// ---------------------------------------------------------------------------
extern "C" void kernel_launch(void* const* d_in, const int* in_sizes, int n_in,
                              void* d_out, int out_size) {
    const float* x   = (const float*)d_in[0];
    const int*   ei  = (const int*)d_in[1];   // int32 view; prep detects dtype
    const float* Ww  = (const float*)d_in[2];
    const float* Wb  = (const float*)d_in[3];
    const float* Bw  = (const float*)d_in[4];
    const float* Bb  = (const float*)d_in[5];
    float*       out = (float*)d_out;

    int E = in_sizes[1] / 2;
    int N = in_sizes[0] / NODE_ELEMS;

    prep_kernel<<<(NNODES + 255) / 256, 256>>>(ei, E);
    count_kernel<<<(E + 255) / 256, 256>>>(ei, E);
    scanfill_kernel<<<1, 1024>>>(ei, E);

    int smem_bytes = IMG_FLOATS * 4 + WT_FLOAT2 * 8;   // 82944 + 18432 = 101376
    cudaFuncSetAttribute(gnn_main_kernel,
                         cudaFuncAttributeMaxDynamicSharedMemorySize, smem_bytes);
    gnn_main_kernel<<<N, 256, smem_bytes>>>(x, Ww, Wb, Bw, Bb, out);
}

// round 9
// speedup vs baseline: 1.6959x; 1.0631x over previous
#include <cuda_runtime.h>

// ---------------------------------------------------------------------------
// SpatioTemporalGNNLayer: out = relu(conv3x3(x,Ww)+Wb + conv3x3(agg,Bw)+Bb)
// agg[dst] = mean over incoming edges of x[src].
//
// Fused per-node kernel, crossbar-byte-aware: thread = 8 cos x 8 px, 4-way
// ci split, warp-uniform weight broadcasts, fma.rn.f32x2, dual-alignment
// smem rows, targeted pad zeroing, smem cross-warp reduction. 256thr x 2 CTA/SM.
// ---------------------------------------------------------------------------

#define NNODES 4096
#define NODE_ELEMS 4096          // 16*16*16
#define RS 36                    // row: [0,x0..x15,0,pad,pad | x0..x15] (144B)
#define CHS (18*RS)              // 648 floats per channel image
#define IMG_FLOATS (32*CHS)      // 20736 (x 16ch + agg 16ch)
#define WT_FLOAT2 2304           // 144q x 16co duplicated pairs (one conv)
#define NMASK (NNODES-1)

__device__ int g_deg[NNODES];
__device__ int g_cur[NNODES];
__device__ int g_off[NNODES + 1];
__device__ int g_srcs[16384 * 4];
__device__ int g_is64;

// ---------------------------------------------------------------------------
__global__ void prep_kernel(const int* __restrict__ ei32, int E) {
    int i = blockIdx.x * blockDim.x + threadIdx.x;
    if (i < NNODES) { g_deg[i] = 0; g_cur[i] = 0; }
    if (blockIdx.x == 0 && threadIdx.x < 32) {
        int n = (E < 32) ? E : 32;
        int odd = (threadIdx.x < n) ? ei32[2 * threadIdx.x + 1] : 0;
        unsigned nz = __ballot_sync(0xffffffffu, odd != 0);
        if (threadIdx.x == 0) g_is64 = (nz == 0);
    }
}

__device__ __forceinline__ int load_idx(const int* ei32, int pos) {
    return g_is64 ? (ei32[2 * pos] & NMASK) : (ei32[pos] & NMASK);
}

__global__ void count_kernel(const int* __restrict__ ei32, int E) {
    int e = blockIdx.x * blockDim.x + threadIdx.x;
    if (e < E) atomicAdd(&g_deg[load_idx(ei32, E + e)], 1);
}

__global__ void scanfill_kernel(const int* __restrict__ ei32, int E) {
    __shared__ int wsum[32];
    int t = threadIdx.x;
    int lane = t & 31, wid = t >> 5;
    int4 v = ((const int4*)g_deg)[t];
    int sum = v.x + v.y + v.z + v.w;
    int s = sum;
#pragma unroll
    for (int d = 1; d < 32; d <<= 1) {
        int n = __shfl_up_sync(0xffffffffu, s, d);
        if (lane >= d) s += n;
    }
    if (lane == 31) wsum[wid] = s;
    __syncthreads();
    if (wid == 0) {
        int ws = wsum[lane];
#pragma unroll
        for (int d = 1; d < 32; d <<= 1) {
            int n = __shfl_up_sync(0xffffffffu, ws, d);
            if (lane >= d) ws += n;
        }
        wsum[lane] = ws;
    }
    __syncthreads();
    int excl = ((wid > 0) ? wsum[wid - 1] : 0) + s - sum;
    g_off[4 * t + 0] = excl;
    g_off[4 * t + 1] = excl + v.x;
    g_off[4 * t + 2] = excl + v.x + v.y;
    g_off[4 * t + 3] = excl + v.x + v.y + v.z;
    if (t == 1023) g_off[NNODES] = wsum[31];
    __syncthreads();
    for (int e = t; e < E; e += 1024) {
        int sc = load_idx(ei32, e);
        int d  = load_idx(ei32, E + e);
        int pos = g_off[d] + atomicAdd(&g_cur[d], 1);
        g_srcs[pos] = sc;
    }
}

// ---------------------------------------------------------------------------
__device__ __forceinline__ float2 ffma2(float2 a, float2 b, float2 c) {
    float2 d;
    asm("{\n\t"
        ".reg .b64 ta, tb, tc;\n\t"
        "mov.b64 ta, {%2, %3};\n\t"
        "mov.b64 tb, {%4, %5};\n\t"
        "mov.b64 tc, {%6, %7};\n\t"
        "fma.rn.f32x2 tc, ta, tb, tc;\n\t"
        "mov.b64 {%0, %1}, tc;\n\t"
        "}"
        : "=f"(d.x), "=f"(d.y)
        : "f"(a.x), "f"(a.y), "f"(b.x), "f"(b.y), "f"(c.x), "f"(c.y));
    return d;
}

// 4-ci-slice conv: this thread's 8 output channels (co0..co0+7) x 8 px
// (pixel pairs j at x = 8*half + 2j) of one output row.
// Row layout (36 floats): [0, x0..x15, 0, pad, pad, x0..x15]
// Weights wt[q*16 + co] = (w,w), q = ci*9 + r*3 + t (warp-uniform address).
__device__ __forceinline__ void conv_slice(const float* __restrict__ img,
                                           const float2* __restrict__ wt,
                                           int ci0, int row, int half, int co0,
                                           float2 acc[8][4]) {
#pragma unroll 1
    for (int cl = 0; cl < 4; cl++) {
        int ci = ci0 + cl;
        const float* ch = img + ci * CHS;
#pragma unroll
        for (int r = 0; r < 3; r++) {
            const float* bp = ch + (row + r) * RS + 8 * half;
            float4 pa = *(const float4*)(bp);
            float4 pb = *(const float4*)(bp + 4);
            float2 pc = *(const float2*)(bp + 8);
            float4 sa = *(const float4*)(bp + 20);
            float4 sb = *(const float4*)(bp + 24);
            float2 P[5] = { make_float2(pa.x, pa.y), make_float2(pa.z, pa.w),
                            make_float2(pb.x, pb.y), make_float2(pb.z, pb.w),
                            pc };
            float2 S[4] = { make_float2(sa.x, sa.y), make_float2(sa.z, sa.w),
                            make_float2(sb.x, sb.y), make_float2(sb.z, sb.w) };
            const float2* wr = wt + (ci * 9 + r * 3) * 16 + co0;
#pragma unroll
            for (int t = 0; t < 3; t++) {
                const float4* wv = (const float4*)(wr + t * 16);
                float4 wA = wv[0], wB = wv[1], wC = wv[2], wD = wv[3];
                float2 w[8] = { make_float2(wA.x, wA.y), make_float2(wA.z, wA.w),
                                make_float2(wB.x, wB.y), make_float2(wB.z, wB.w),
                                make_float2(wC.x, wC.y), make_float2(wC.z, wC.w),
                                make_float2(wD.x, wD.y), make_float2(wD.z, wD.w) };
#pragma unroll
                for (int c = 0; c < 8; c++) {
#pragma unroll
                    for (int j = 0; j < 4; j++) {
                        float2 op = (t == 0) ? P[j] : (t == 1) ? S[j] : P[j + 1];
                        acc[c][j] = ffma2(w[c], op, acc[c][j]);
                    }
                }
            }
        }
    }
}

__global__ __launch_bounds__(256, 2) void gnn_main_kernel(
    const float* __restrict__ x,
    const float* __restrict__ Ww, const float* __restrict__ Wbias,
    const float* __restrict__ Bw, const float* __restrict__ Bbias,
    float* __restrict__ out) {
    extern __shared__ float sm[];
    float*  sImg = sm;                          // 20736 floats
    float2* sWt  = (float2*)(sm + IMG_FLOATS);  // 2304 float2 (one conv)

    int tid  = threadIdx.x;
    int node = blockIdx.x;

    // targeted pad zeroing (only bytes the conv reads that scatter won't write)
    // rows 0 and 17 of every channel: 9 float4 each
    for (int i = tid; i < 32 * 18; i += 256) {
        int ch = i / 18, k = i % 18;
        int off = ch * CHS + ((k < 9) ? 0 : (17 * RS - 36)) + k * 4;  // k>=9 maps to row17
        ((float4*)(sImg + ch * CHS))[0] = ((float4*)(sImg + ch * CHS))[0]; // no-op guard
        // compute cleanly:
        int row17 = (k < 9) ? 0 : 17 * RS;
        int q = (k < 9) ? k : (k - 9);
        *(float4*)(sImg + ch * CHS + row17 + q * 4) = make_float4(0.f, 0.f, 0.f, 0.f);
        (void)off;
    }
    // words 0 and 17 of rows 1..16 of every channel
    for (int i = tid; i < 32 * 16; i += 256) {
        int ch = i >> 4, y = i & 15;
        float* b = sImg + ch * CHS + (y + 1) * RS;
        b[0] = 0.f; b[17] = 0.f;
    }
    // stage phase-A (Ww): wt[q*16 + co] = (w,w), q = ci*9+r*3+t
    for (int i = tid; i < WT_FLOAT2; i += 256) {
        int co = i & 15, q = i >> 4;
        float v = Ww[co * 144 + q];
        sWt[i] = make_float2(v, v);
    }

    // gather-mean over incoming edges: 4 float4 per thread (regs)
    const float4* xp = (const float4*)(x + (size_t)node * NODE_ELEMS);
    float4 a[4];
#pragma unroll
    for (int k = 0; k < 4; k++) a[k] = make_float4(0.f, 0.f, 0.f, 0.f);
    int beg = g_off[node], end = g_off[node + 1];
    for (int e = beg; e < end; e++) {
        int sc = g_srcs[e] & NMASK;
        const float4* sp = (const float4*)(x + (size_t)sc * NODE_ELEMS);
#pragma unroll
        for (int k = 0; k < 4; k++) {
            float4 v = __ldg(&sp[tid + 256 * k]);
            a[k].x += v.x; a[k].y += v.y; a[k].z += v.z; a[k].w += v.w;
        }
    }
    float inv = 1.0f / (float)max(end - beg, 1);

    __syncthreads();   // pads zeroed + Ww staged

    // scatter x + agg into dual-alignment rows
#pragma unroll
    for (int k = 0; k < 4; k++) {
        int i4  = tid + 256 * k;
        int ci  = i4 >> 6;
        int rem = i4 & 63;
        int y   = rem >> 2;
        int m   = (rem & 3) * 4;
        float* bx = sImg + ci * CHS + (y + 1) * RS;
        float* ba = sImg + (16 + ci) * CHS + (y + 1) * RS;
        float4 xv = xp[i4];
        bx[1 + m] = xv.x; bx[2 + m] = xv.y; bx[3 + m] = xv.z; bx[4 + m] = xv.w;
        *(float4*)(bx + 20 + m) = xv;
        float4 av = make_float4(a[k].x * inv, a[k].y * inv, a[k].z * inv, a[k].w * inv);
        ba[1 + m] = av.x; ba[2 + m] = av.y; ba[3 + m] = av.z; ba[4 + m] = av.w;
        *(float4*)(ba + 20 + m) = av;
    }
    __syncthreads();

    // thread map: warp w -> (ci-group cig = w>>1, co-group cog = w&1)
    //             lane   -> row = lane&15, half = lane>>4
    int lane = tid & 31;
    int w    = tid >> 5;
    int row  = lane & 15;
    int half = lane >> 4;
    int cog  = w & 1;
    int cig  = w >> 1;
    int co0  = cog * 8;
    int ci0  = cig * 4;

    float2 acc[8][4];
#pragma unroll
    for (int c = 0; c < 8; c++)
#pragma unroll
        for (int j = 0; j < 4; j++) acc[c][j] = make_float2(0.f, 0.f);

    // phase A: conv(x, Ww) over this warp's 4-ci slice
    conv_slice(sImg, sWt, ci0, row, half, co0, acc);

    __syncthreads();   // done reading Ww
    for (int i = tid; i < WT_FLOAT2; i += 256) {
        int co = i & 15, q = i >> 4;
        float v = Bw[co * 144 + q];
        sWt[i] = make_float2(v, v);
    }
    __syncthreads();

    // phase B: conv(agg, Bw)
    conv_slice(sImg + 16 * CHS, sWt, ci0, row, half, co0, acc);

    // cross-warp reduction over 4 ci-groups (reuse sImg; 48KB)
    __syncthreads();
    float4* red = (float4*)sImg;
    int slot = cog * 32 + lane;            // 0..63
    if (cig > 0) {
        int p = cig - 1;
#pragma unroll
        for (int c = 0; c < 8; c++) {
            red[((p * 16 + 2 * c + 0) * 64) + slot] =
                make_float4(acc[c][0].x, acc[c][0].y, acc[c][1].x, acc[c][1].y);
            red[((p * 16 + 2 * c + 1) * 64) + slot] =
                make_float4(acc[c][2].x, acc[c][2].y, acc[c][3].x, acc[c][3].y);
        }
    }
    __syncthreads();
    if (cig == 0) {
#pragma unroll
        for (int c = 0; c < 8; c++) {
            int co = co0 + c;
            float bz = __ldg(&Wbias[co]) + __ldg(&Bbias[co]);
            float4 v0 = make_float4(acc[c][0].x, acc[c][0].y, acc[c][1].x, acc[c][1].y);
            float4 v1 = make_float4(acc[c][2].x, acc[c][2].y, acc[c][3].x, acc[c][3].y);
#pragma unroll
            for (int p = 0; p < 3; p++) {
                float4 r0 = red[((p * 16 + 2 * c + 0) * 64) + slot];
                float4 r1 = red[((p * 16 + 2 * c + 1) * 64) + slot];
                v0.x += r0.x; v0.y += r0.y; v0.z += r0.z; v0.w += r0.w;
                v1.x += r1.x; v1.y += r1.y; v1.z += r1.z; v1.w += r1.w;
            }
            float* o = out + (size_t)node * NODE_ELEMS + co * 256
                       + row * 16 + 8 * half;
            ((float4*)o)[0] = make_float4(fmaxf(v0.x + bz, 0.f), fmaxf(v0.y + bz, 0.f),
                                          fmaxf(v0.z + bz, 0.f), fmaxf(v0.w + bz, 0.f));
            ((float4*)o)[1] = make_float4(fmaxf(v1.x + bz, 0.f), fmaxf(v1.y + bz, 0.f),
                                          fmaxf(v1.z + bz, 0.f), fmaxf(v1.w + bz, 0.f));
        }
    }
}

// ---------------------------------------------------------------------------
extern "C" void kernel_launch(void* const* d_in, const int* in_sizes, int n_in,
                              void* d_out, int out_size) {
    const float* x   = (const float*)d_in[0];
    const int*   ei  = (const int*)d_in[1];   // int32 view; prep detects dtype
    const float* Ww  = (const float*)d_in[2];
    const float* Wb  = (const float*)d_in[3];
    const float* Bw  = (const float*)d_in[4];
    const float* Bb  = (const float*)d_in[5];
    float*       out = (float*)d_out;

    int E = in_sizes[1] / 2;
    int N = in_sizes[0] / NODE_ELEMS;

    prep_kernel<<<(NNODES + 255) / 256, 256>>>(ei, E);
    count_kernel<<<(E + 255) / 256, 256>>>(ei, E);
    scanfill_kernel<<<1, 1024>>>(ei, E);

    int smem_bytes = IMG_FLOATS * 4 + WT_FLOAT2 * 8;   // 101376
    cudaFuncSetAttribute(gnn_main_kernel,
                         cudaFuncAttributeMaxDynamicSharedMemorySize, smem_bytes);
    gnn_main_kernel<<<N, 256, smem_bytes>>>(x, Ww, Wb, Bw, Bb, out);
}